// round 11
// baseline (speedup 1.0000x reference)
#include <cuda_runtime.h>
#include <math.h>

#define N_NODES 50000
#define N_EDGES 800000

// ---- scratch (device globals; no allocation allowed) ----
__device__ __align__(16) float g_h1[N_NODES * 256];
__device__ __align__(16) float g_h2[N_NODES * 256];
__device__ __align__(16) float g_z [N_NODES * 256];
__device__ float g_sim[N_EDGES];          // CSR order, raw thresholded sims
__device__ float g_w  [N_EDGES];          // compacted exp-weights
__device__ int   g_ccol[N_EDGES];         // CSR order: col of slot j
__device__ int   g_ccol2[N_EDGES];        // compacted cols
__device__ int   g_crow[N_EDGES];         // CSR order: row of slot j
__device__ float g_rnrm[N_NODES];
__device__ float g_wself[N_NODES];
__device__ int   g_rowptr[N_NODES + 1];
__device__ int   g_rowend[N_NODES];       // end of compacted segment
__device__ int   g_wr[N_NODES];
__device__ int   g_cnt[N_NODES];

// ================= CSR build (row/col fixed across the 3 layers) =============
__global__ void k_zero_cnt() {
    int i = blockIdx.x * blockDim.x + threadIdx.x;
    if (i < N_NODES) g_cnt[i] = 0;
}

__global__ void k_hist(const int* __restrict__ row) {
    for (int e = blockIdx.x * blockDim.x + threadIdx.x; e < N_EDGES;
         e += gridDim.x * blockDim.x)
        atomicAdd(&g_cnt[row[e]], 1);
}

// single-block scan, chunk-per-thread: two L2 passes, one block-wide scan
__global__ void __launch_bounds__(1024) k_scan_fast() {
    constexpr int CH = (N_NODES + 1023) / 1024;   // 49
    __shared__ int wsum[32];
    int tid = threadIdx.x, lane = tid & 31, wid = tid >> 5;
    int base = tid * CH;
    int lsum = 0;
#pragma unroll 7
    for (int i = 0; i < CH; i++) {
        int idx = base + i;
        if (idx < N_NODES) lsum += g_cnt[idx];
    }
    int inc = lsum;
#pragma unroll
    for (int o = 1; o < 32; o <<= 1) {
        int y = __shfl_up_sync(0xffffffffu, inc, o);
        if (lane >= o) inc += y;
    }
    if (lane == 31) wsum[wid] = inc;
    __syncthreads();
    if (wid == 0) {
        int w = wsum[lane];
#pragma unroll
        for (int o = 1; o < 32; o <<= 1) {
            int y = __shfl_up_sync(0xffffffffu, w, o);
            if (lane >= o) w += y;
        }
        wsum[lane] = w;
    }
    __syncthreads();
    int excl = (wid ? wsum[wid - 1] : 0) + inc - lsum;
    int run = excl;
#pragma unroll 7
    for (int i = 0; i < CH; i++) {
        int idx = base + i;
        if (idx < N_NODES) {
            g_rowptr[idx] = run;
            g_wr[idx] = run;
            run += g_cnt[idx];
        }
    }
    if (tid == 1023) g_rowptr[N_NODES] = run;
}

__global__ void k_scatter(const int* __restrict__ row, const int* __restrict__ col) {
    for (int e = blockIdx.x * blockDim.x + threadIdx.x; e < N_EDGES;
         e += gridDim.x * blockDim.x) {
        int r = row[e];
        int p = atomicAdd(&g_wr[r], 1);
        g_ccol[p] = col[e];
        g_crow[p] = r;
    }
}

// ================= per-layer kernels =========================================
// reciprocal node norms (raw x only; later layers fold into agg)
template <int IN>
__global__ void k_norms(const float* __restrict__ x) {
    int n = (blockIdx.x * blockDim.x + threadIdx.x) >> 5;
    if (n >= N_NODES) return;
    int lane = threadIdx.x & 31;
    const float4* xr = (const float4*)(x + (size_t)n * IN);
    float s = 0.0f;
#pragma unroll
    for (int i = 0; i < IN / 128; i++) {
        float4 v = xr[lane + 32 * i];
        s += v.x * v.x + v.y * v.y + v.z * v.z + v.w * v.w;
    }
#pragma unroll
    for (int o = 16; o; o >>= 1) s += __shfl_xor_sync(0xffffffffu, s, o);
    if (lane == 0) g_rnrm[n] = 1.0f / fmaxf(sqrtf(s), 1e-12f);
}

// warp-per-U-CSR-slots SDDMM, loads front-batched for MLP.
template <int IN, int U>
__global__ void k_sim(const float* __restrict__ x) {
    int w = (blockIdx.x * blockDim.x + threadIdx.x) >> 5;
    int j0 = w * U;
    if (j0 >= N_EDGES) return;
    int lane = threadIdx.x & 31;
    constexpr int V = IN / 128;
    int rr[U], cc[U];
#pragma unroll
    for (int u = 0; u < U; u++) {
        int j = j0 + u;
        if (j > N_EDGES - 1) j = N_EDGES - 1;
        rr[u] = g_crow[j];
        cc[u] = g_ccol[j];
    }
    float4 a[U][V], b[U][V];
#pragma unroll
    for (int u = 0; u < U; u++) {
        const float4* xa = (const float4*)(x + (size_t)rr[u] * IN);
        const float4* xb = (const float4*)(x + (size_t)cc[u] * IN);
#pragma unroll
        for (int i = 0; i < V; i++) {
            a[u][i] = xa[lane + 32 * i];
            b[u][i] = xb[lane + 32 * i];
        }
    }
    float s[U];
#pragma unroll
    for (int u = 0; u < U; u++) {
        float t = 0.0f;
#pragma unroll
        for (int i = 0; i < V; i++)
            t += a[u][i].x * b[u][i].x + a[u][i].y * b[u][i].y +
                 a[u][i].z * b[u][i].z + a[u][i].w * b[u][i].w;
        s[u] = t;
    }
#pragma unroll
    for (int o = 16; o; o >>= 1)
#pragma unroll
        for (int u = 0; u < U; u++) s[u] += __shfl_xor_sync(0xffffffffu, s[u], o);
    if (lane == 0) {
#pragma unroll
        for (int u = 0; u < U; u++) {
            int j = j0 + u;
            if (j < N_EDGES) {
                float sim = s[u] * g_rnrm[rr[u]] * g_rnrm[cc[u]];
                g_sim[j] = (sim < 0.1f) ? 0.0f : sim;
            }
        }
    }
}

// rowsum + degree + nonzero compaction + exp-weight precompute (warp per node)
__global__ void k_rowdeg() {
    int n = (blockIdx.x * blockDim.x + threadIdx.x) >> 5;
    if (n >= N_NODES) return;
    int lane = threadIdx.x & 31;
    int b = g_rowptr[n], e2 = g_rowptr[n + 1];
    float s = 0.0f;
    int cnt = 0;
    int wpos = b;
    for (int base = b; base < e2; base += 32) {
        int j = base + lane;
        float v = (j < e2) ? g_sim[j] : 0.0f;
        int c = (j < e2) ? g_ccol[j] : 0;
        bool nz = (v != 0.0f);
        unsigned m = __ballot_sync(0xffffffffu, nz);
        int pos = __popc(m & ((1u << lane) - 1u));
        if (nz) {
            g_w[wpos + pos] = v;
            g_ccol2[wpos + pos] = c;
        }
        s += v;
        cnt += nz;
        wpos += __popc(m);
    }
#pragma unroll
    for (int o = 16; o; o >>= 1) {
        s += __shfl_xor_sync(0xffffffffu, s, o);
        cnt += __shfl_xor_sync(0xffffffffu, cnt, o);
    }
    float irs = (s > 0.0f) ? (1.0f / s) : 0.0f;
    for (int j = b + lane; j < wpos; j += 32) g_w[j] = __expf(g_w[j] * irs);
    if (lane == 0) {
        g_rowend[n] = wpos;
        g_wself[n] = __expf(1.0f / (float)(cnt + 1));
    }
}

// ====== 8x8 register-tiled SGEMM, one head per blockIdx.y ======
template <int IN>
__global__ void __launch_bounds__(128) k_gemm8(const float* __restrict__ X,
                                               const float* __restrict__ W,
                                               float* __restrict__ Z,
                                               int OUTF) {
    constexpr int BM = 128, BN = 64, BK = 16;
    __shared__ float sXT[BK][BM + 4];
    __shared__ float sW[BK][BN + 4];
    int tid = threadIdx.x;
    int n0 = blockIdx.x * BM;
    int h = blockIdx.y;
    int f0 = h * BN;
    int tx = tid & 7, ty = tid >> 3;
    float acc[8][8];
#pragma unroll
    for (int i = 0; i < 8; i++)
#pragma unroll
        for (int jj = 0; jj < 8; jj++) acc[i][jj] = 0.0f;

    for (int k0 = 0; k0 < IN; k0 += BK) {
        {
            int n = n0 + tid;
#pragma unroll
            for (int i = 0; i < 4; i++) {
                float4 v = (n < N_NODES)
                               ? *(const float4*)&X[(size_t)n * IN + k0 + i * 4]
                               : make_float4(0.f, 0.f, 0.f, 0.f);
                sXT[i * 4 + 0][tid] = v.x;
                sXT[i * 4 + 1][tid] = v.y;
                sXT[i * 4 + 2][tid] = v.z;
                sXT[i * 4 + 3][tid] = v.w;
            }
        }
        {
#pragma unroll
            for (int t = 0; t < 2; t++) {
                int idx = tid + t * 128;
                int kk = idx >> 4, f4 = (idx & 15) * 4;
                *(float4*)&sW[kk][f4] =
                    *(const float4*)&W[((size_t)h * IN + k0 + kk) * 64 + f4];
            }
        }
        __syncthreads();
#pragma unroll
        for (int k = 0; k < BK; k++) {
            float av[8], bv[8];
            *(float4*)(av + 0) = *(const float4*)&sXT[k][ty * 8 + 0];
            *(float4*)(av + 4) = *(const float4*)&sXT[k][ty * 8 + 4];
            *(float4*)(bv + 0) = *(const float4*)&sW[k][tx * 8 + 0];
            *(float4*)(bv + 4) = *(const float4*)&sW[k][tx * 8 + 4];
#pragma unroll
            for (int i = 0; i < 8; i++)
#pragma unroll
                for (int jj = 0; jj < 8; jj++) acc[i][jj] += av[i] * bv[jj];
        }
        __syncthreads();
    }
#pragma unroll
    for (int i = 0; i < 8; i++) {
        int n = n0 + ty * 8 + i;
        if (n < N_NODES) {
            float4 v0 = make_float4(acc[i][0], acc[i][1], acc[i][2], acc[i][3]);
            float4 v1 = make_float4(acc[i][4], acc[i][5], acc[i][6], acc[i][7]);
            *(float4*)&Z[(size_t)n * OUTF + f0 + tx * 8 + 0] = v0;
            *(float4*)&Z[(size_t)n * OUTF + f0 + tx * 8 + 4] = v1;
        }
    }
}

// small GEMM for layer 2: Z[n, o] = sum_d X[n,d] * W2[d,o], OUTF=16
__global__ void __launch_bounds__(256) k_gemm16(const float* __restrict__ X,
                                                const float* __restrict__ W,
                                                float* __restrict__ Z) {
    constexpr int IN = 256, BM = 64, BK = 16;
    __shared__ float sXT[BK][BM + 4];
    __shared__ float sW[BK][16 + 4];
    int tid = threadIdx.x;
    int tx = tid % 16, ty = tid / 16;
    int n0 = blockIdx.x * BM;
    float acc[4] = {0.f, 0.f, 0.f, 0.f};
    for (int k0 = 0; k0 < IN; k0 += BK) {
        {
            int r = tid >> 2, c4 = (tid & 3) * 4;
            int n = n0 + r;
            float4 v = (n < N_NODES)
                           ? *(const float4*)&X[(size_t)n * IN + k0 + c4]
                           : make_float4(0.f, 0.f, 0.f, 0.f);
            sXT[c4 + 0][r] = v.x;
            sXT[c4 + 1][r] = v.y;
            sXT[c4 + 2][r] = v.z;
            sXT[c4 + 3][r] = v.w;
        }
        if (tid < 64) {
            int kk = tid >> 2, f4 = (tid & 3) * 4;
            *(float4*)&sW[kk][f4] = *(const float4*)&W[(size_t)(k0 + kk) * 16 + f4];
        }
        __syncthreads();
#pragma unroll
        for (int k = 0; k < BK; k++) {
            float w = sW[k][tx];
            float4 a = *(const float4*)&sXT[k][ty * 4];
            acc[0] += a.x * w;
            acc[1] += a.y * w;
            acc[2] += a.z * w;
            acc[3] += a.w * w;
        }
        __syncthreads();
    }
#pragma unroll
    for (int i = 0; i < 4; i++) {
        int n = n0 + ty * 4 + i;
        if (n < N_NODES) Z[(size_t)n * 16 + tx] = acc[i];
    }
}

// warp-per-node aggregation over compacted weights (256-wide), float4 gathers,
// 2-unrolled; fused leaky-relu and optional output-row reciprocal norm.
template <bool RELU, bool WRITENORM>
__global__ void k_agg(const float* __restrict__ z, float* __restrict__ out) {
    constexpr int OUTF = 256;
    int n = (blockIdx.x * blockDim.x + threadIdx.x) >> 5;
    if (n >= N_NODES) return;
    int lane = threadIdx.x & 31;
    float ws = g_wself[n];
    float4 acc[2];
    const float4* zn = (const float4*)(z + (size_t)n * OUTF);
#pragma unroll
    for (int i = 0; i < 2; i++) {
        float4 v = zn[lane + 32 * i];
        acc[i] = make_float4(ws * v.x, ws * v.y, ws * v.z, ws * v.w);
    }
    int b = g_rowptr[n], e2 = g_rowend[n];
    int j = b;
    for (; j + 2 <= e2; j += 2) {
        float w0 = g_w[j], w1 = g_w[j + 1];
        int c0 = g_ccol2[j], c1 = g_ccol2[j + 1];
        const float4* z0 = (const float4*)(z + (size_t)c0 * OUTF);
        const float4* z1 = (const float4*)(z + (size_t)c1 * OUTF);
#pragma unroll
        for (int i = 0; i < 2; i++) {
            float4 v0 = z0[lane + 32 * i];
            float4 v1 = z1[lane + 32 * i];
            acc[i].x += w0 * v0.x + w1 * v1.x;
            acc[i].y += w0 * v0.y + w1 * v1.y;
            acc[i].z += w0 * v0.z + w1 * v1.z;
            acc[i].w += w0 * v0.w + w1 * v1.w;
        }
    }
    if (j < e2) {
        float w0 = g_w[j];
        const float4* z0 = (const float4*)(z + (size_t)g_ccol2[j] * OUTF);
#pragma unroll
        for (int i = 0; i < 2; i++) {
            float4 v0 = z0[lane + 32 * i];
            acc[i].x += w0 * v0.x;
            acc[i].y += w0 * v0.y;
            acc[i].z += w0 * v0.z;
            acc[i].w += w0 * v0.w;
        }
    }
    float nrm = 0.0f;
#pragma unroll
    for (int i = 0; i < 2; i++) {
        float4 v = acc[i];
        if (RELU) {
            v.x = (v.x >= 0.f) ? v.x : 0.01f * v.x;
            v.y = (v.y >= 0.f) ? v.y : 0.01f * v.y;
            v.z = (v.z >= 0.f) ? v.z : 0.01f * v.z;
            v.w = (v.w >= 0.f) ? v.w : 0.01f * v.w;
        }
        if (WRITENORM)
            nrm += v.x * v.x + v.y * v.y + v.z * v.z + v.w * v.w;
        ((float4*)(out + (size_t)n * OUTF))[lane + 32 * i] = v;
    }
    if (WRITENORM) {
#pragma unroll
        for (int o = 16; o; o >>= 1) nrm += __shfl_xor_sync(0xffffffffu, nrm, o);
        if (lane == 0) g_rnrm[n] = 1.0f / fmaxf(sqrtf(nrm), 1e-12f);
    }
}

// 16-wide aggregation: two nodes per warp (half-warp each), compacted weights.
__global__ void k_agg16(const float* __restrict__ z, float* __restrict__ out) {
    int w = (blockIdx.x * blockDim.x + threadIdx.x) >> 5;
    int lane = threadIdx.x & 31;
    int n = w * 2 + (lane >> 4);
    if (n >= N_NODES) return;
    int l = lane & 15;
    float acc = g_wself[n] * z[(size_t)n * 16 + l];
    int b = g_rowptr[n], e2 = g_rowend[n];
    int j = b;
    for (; j + 2 <= e2; j += 2) {
        float w0 = g_w[j], w1 = g_w[j + 1];
        int c0 = g_ccol2[j], c1 = g_ccol2[j + 1];
        acc += w0 * z[(size_t)c0 * 16 + l] + w1 * z[(size_t)c1 * 16 + l];
    }
    if (j < e2) acc += g_w[j] * z[(size_t)g_ccol2[j] * 16 + l];
    out[(size_t)n * 16 + l] = acc;
}

// ================= driver ====================================================
extern "C" void kernel_launch(void* const* d_in, const int* in_sizes, int n_in,
                              void* d_out, int out_size) {
    const float* x  = (const float*)d_in[0];
    const float* W0 = (const float*)d_in[1];   // [4,128,64]
    const float* W1 = (const float*)d_in[2];   // [4,256,64]
    const float* W2 = (const float*)d_in[3];   // [1,256,16]
    const int*   row = (const int*)d_in[4];
    const int*   col = (const int*)d_in[5];
    float* out = (float*)d_out;

    float *h1, *h2, *z;
    cudaGetSymbolAddress((void**)&h1, g_h1);
    cudaGetSymbolAddress((void**)&h2, g_h2);
    cudaGetSymbolAddress((void**)&z,  g_z);

    // side stream + events, created once (host objects only; no device memory)
    static cudaStream_t s1 = nullptr;
    static cudaEvent_t ev[8];
    if (s1 == nullptr) {
        cudaStreamCreateWithFlags(&s1, cudaStreamNonBlocking);
        for (int i = 0; i < 8; i++)
            cudaEventCreateWithFlags(&ev[i], cudaEventDisableTiming);
    }

    const int NODE_WARP_BLOCKS = (N_NODES * 32 + 255) / 256;        // 6250
    const int SIM4_BLOCKS = ((N_EDGES + 3) / 4 * 32 + 255) / 256;   // 25000
    const int SIM2_BLOCKS = ((N_EDGES + 1) / 2 * 32 + 255) / 256;   // 50000
    const int GEMM_MB = (N_NODES + 127) / 128;                      // 391

    // ---- fork: gemm0 + norms on s1 (need only x/W0), CSR build on s0 ----
    cudaEventRecord(ev[0], 0);
    cudaStreamWaitEvent(s1, ev[0], 0);
    k_norms<128><<<NODE_WARP_BLOCKS, 256, 0, s1>>>(x);
    cudaEventRecord(ev[7], s1);           // norms done (needed before sim0)
    k_gemm8<128><<<dim3(GEMM_MB, 4), 128, 0, s1>>>(x, W0, z, 256);
    cudaEventRecord(ev[1], s1);           // gemm0 done

    // s0: CSR build
    k_zero_cnt<<<(N_NODES + 255) / 256, 256>>>();
    k_hist<<<400, 256>>>(row);
    k_scan_fast<<<1, 1024>>>();
    k_scatter<<<400, 256>>>(row, col);

    // s0: sim0 (CSR-ordered; waits on norms from s1) + rowdeg0
    cudaStreamWaitEvent(0, ev[7], 0);
    k_sim<128, 4><<<SIM4_BLOCKS, 256>>>(x);
    k_rowdeg<<<NODE_WARP_BLOCKS, 256>>>();

    // join gemm0, aggregate -> h1 (relu + write next-layer norms)
    cudaStreamWaitEvent(0, ev[1], 0);
    k_agg<true, true><<<NODE_WARP_BLOCKS, 256>>>(z, h1);

    // ---- layer 1: gemm1 on s1  ||  sim1+rowdeg1 on s0 ----
    cudaEventRecord(ev[2], 0);
    cudaStreamWaitEvent(s1, ev[2], 0);
    k_gemm8<256><<<dim3(GEMM_MB, 4), 128, 0, s1>>>(h1, W1, z, 256);
    cudaEventRecord(ev[3], s1);
    k_sim<256, 2><<<SIM2_BLOCKS, 256>>>(h1);
    k_rowdeg<<<NODE_WARP_BLOCKS, 256>>>();
    cudaStreamWaitEvent(0, ev[3], 0);
    k_agg<true, true><<<NODE_WARP_BLOCKS, 256>>>(z, h2);

    // ---- layer 2: gemm2 on s1  ||  sim2+rowdeg2 on s0 ----
    cudaEventRecord(ev[4], 0);
    cudaStreamWaitEvent(s1, ev[4], 0);
    k_gemm16<<<(N_NODES + 63) / 64, 256, 0, s1>>>(h2, W2, z);
    cudaEventRecord(ev[5], s1);
    k_sim<256, 2><<<SIM2_BLOCKS, 256>>>(h2);
    k_rowdeg<<<NODE_WARP_BLOCKS, 256>>>();
    cudaStreamWaitEvent(0, ev[5], 0);
    k_agg16<<<(N_NODES / 2 * 32 + 255) / 256, 256>>>(z, out);
}

// round 12
// speedup vs baseline: 1.5251x; 1.5251x over previous
#include <cuda_runtime.h>
#include <math.h>

#define N_NODES 50000
#define N_EDGES 800000

// ---- scratch (device globals; no allocation allowed) ----
__device__ __align__(16) float g_h1[N_NODES * 256];
__device__ __align__(16) float g_h2[N_NODES * 256];
__device__ __align__(16) float g_z [N_NODES * 256];
__device__ float g_sim[N_EDGES];          // CSR order, raw thresholded sims
__device__ float g_w  [N_EDGES];          // compacted exp-weights
__device__ int   g_ccol[N_EDGES];         // CSR order: col of slot j
__device__ int   g_ccol2[N_EDGES];        // compacted cols
__device__ int   g_crow[N_EDGES];         // CSR order: row of slot j
__device__ float g_rnrm[N_NODES];
__device__ float g_wself[N_NODES];
__device__ int   g_rowptr[N_NODES + 1];
__device__ int   g_rowend[N_NODES];       // end of compacted segment
__device__ int   g_wr[N_NODES];
__device__ int   g_cnt[N_NODES];

// ================= CSR build (row/col fixed across the 3 layers) =============
__global__ void k_hist(const int* __restrict__ row) {
    for (int e = blockIdx.x * blockDim.x + threadIdx.x; e < N_EDGES;
         e += gridDim.x * blockDim.x)
        atomicAdd(&g_cnt[row[e]], 1);
}

// single-block scan, chunk-per-thread: two passes + one block-wide scan
__global__ void __launch_bounds__(1024) k_scan_fast() {
    constexpr int CH = (N_NODES + 1023) / 1024;   // 49
    __shared__ int wsum[32];
    int tid = threadIdx.x, lane = tid & 31, wid = tid >> 5;
    int base = tid * CH;
    int lsum = 0;
#pragma unroll 7
    for (int i = 0; i < CH; i++) {
        int idx = base + i;
        if (idx < N_NODES) lsum += g_cnt[idx];
    }
    int inc = lsum;
#pragma unroll
    for (int o = 1; o < 32; o <<= 1) {
        int y = __shfl_up_sync(0xffffffffu, inc, o);
        if (lane >= o) inc += y;
    }
    if (lane == 31) wsum[wid] = inc;
    __syncthreads();
    if (wid == 0) {
        int w = wsum[lane];
#pragma unroll
        for (int o = 1; o < 32; o <<= 1) {
            int y = __shfl_up_sync(0xffffffffu, w, o);
            if (lane >= o) w += y;
        }
        wsum[lane] = w;
    }
    __syncthreads();
    int excl = (wid ? wsum[wid - 1] : 0) + inc - lsum;
    int run = excl;
#pragma unroll 7
    for (int i = 0; i < CH; i++) {
        int idx = base + i;
        if (idx < N_NODES) {
            g_rowptr[idx] = run;
            g_wr[idx] = run;
            run += g_cnt[idx];
        }
    }
    if (tid == 1023) g_rowptr[N_NODES] = run;
}

__global__ void k_scatter(const int* __restrict__ row, const int* __restrict__ col) {
    for (int e = blockIdx.x * blockDim.x + threadIdx.x; e < N_EDGES;
         e += gridDim.x * blockDim.x) {
        int r = row[e];
        int p = atomicAdd(&g_wr[r], 1);
        g_ccol[p] = col[e];
        g_crow[p] = r;
    }
}

// ================= per-layer kernels =========================================
// reciprocal node norms (raw x only; later layers fold into agg)
template <int IN>
__global__ void k_norms(const float* __restrict__ x) {
    int n = (blockIdx.x * blockDim.x + threadIdx.x) >> 5;
    if (n >= N_NODES) return;
    int lane = threadIdx.x & 31;
    const float4* xr = (const float4*)(x + (size_t)n * IN);
    float s = 0.0f;
#pragma unroll
    for (int i = 0; i < IN / 128; i++) {
        float4 v = xr[lane + 32 * i];
        s += v.x * v.x + v.y * v.y + v.z * v.z + v.w * v.w;
    }
#pragma unroll
    for (int o = 16; o; o >>= 1) s += __shfl_xor_sync(0xffffffffu, s, o);
    if (lane == 0) g_rnrm[n] = 1.0f / fmaxf(sqrtf(s), 1e-12f);
}

// warp-per-U-CSR-slots SDDMM, loads front-batched for MLP.
template <int IN, int U>
__global__ void k_sim(const float* __restrict__ x) {
    int w = (blockIdx.x * blockDim.x + threadIdx.x) >> 5;
    int j0 = w * U;
    if (j0 >= N_EDGES) return;
    int lane = threadIdx.x & 31;
    constexpr int V = IN / 128;
    int rr[U], cc[U];
#pragma unroll
    for (int u = 0; u < U; u++) {
        int j = j0 + u;
        if (j > N_EDGES - 1) j = N_EDGES - 1;
        rr[u] = g_crow[j];
        cc[u] = g_ccol[j];
    }
    float4 a[U][V], b[U][V];
#pragma unroll
    for (int u = 0; u < U; u++) {
        const float4* xa = (const float4*)(x + (size_t)rr[u] * IN);
        const float4* xb = (const float4*)(x + (size_t)cc[u] * IN);
#pragma unroll
        for (int i = 0; i < V; i++) {
            a[u][i] = xa[lane + 32 * i];
            b[u][i] = xb[lane + 32 * i];
        }
    }
    float s[U];
#pragma unroll
    for (int u = 0; u < U; u++) {
        float t = 0.0f;
#pragma unroll
        for (int i = 0; i < V; i++)
            t += a[u][i].x * b[u][i].x + a[u][i].y * b[u][i].y +
                 a[u][i].z * b[u][i].z + a[u][i].w * b[u][i].w;
        s[u] = t;
    }
#pragma unroll
    for (int o = 16; o; o >>= 1)
#pragma unroll
        for (int u = 0; u < U; u++) s[u] += __shfl_xor_sync(0xffffffffu, s[u], o);
    if (lane == 0) {
#pragma unroll
        for (int u = 0; u < U; u++) {
            int j = j0 + u;
            if (j < N_EDGES) {
                float sim = s[u] * g_rnrm[rr[u]] * g_rnrm[cc[u]];
                g_sim[j] = (sim < 0.1f) ? 0.0f : sim;
            }
        }
    }
}

// rowsum + degree + nonzero compaction + exp-weight precompute (warp per node)
__global__ void k_rowdeg() {
    int n = (blockIdx.x * blockDim.x + threadIdx.x) >> 5;
    if (n >= N_NODES) return;
    int lane = threadIdx.x & 31;
    int b = g_rowptr[n], e2 = g_rowptr[n + 1];
    float s = 0.0f;
    int cnt = 0;
    int wpos = b;
    for (int base = b; base < e2; base += 32) {
        int j = base + lane;
        float v = (j < e2) ? g_sim[j] : 0.0f;
        int c = (j < e2) ? g_ccol[j] : 0;
        bool nz = (v != 0.0f);
        unsigned m = __ballot_sync(0xffffffffu, nz);
        int pos = __popc(m & ((1u << lane) - 1u));
        if (nz) {
            g_w[wpos + pos] = v;
            g_ccol2[wpos + pos] = c;
        }
        s += v;
        cnt += nz;
        wpos += __popc(m);
    }
#pragma unroll
    for (int o = 16; o; o >>= 1) {
        s += __shfl_xor_sync(0xffffffffu, s, o);
        cnt += __shfl_xor_sync(0xffffffffu, cnt, o);
    }
    float irs = (s > 0.0f) ? (1.0f / s) : 0.0f;
    for (int j = b + lane; j < wpos; j += 32) g_w[j] = __expf(g_w[j] * irs);
    if (lane == 0) {
        g_rowend[n] = wpos;
        g_wself[n] = __expf(1.0f / (float)(cnt + 1));
    }
}

// ====== 8x8 register-tiled SGEMM, one head per blockIdx.y ======
template <int IN>
__global__ void __launch_bounds__(128) k_gemm8(const float* __restrict__ X,
                                               const float* __restrict__ W,
                                               float* __restrict__ Z,
                                               int OUTF) {
    constexpr int BM = 128, BN = 64, BK = 16;
    __shared__ float sXT[BK][BM + 4];
    __shared__ float sW[BK][BN + 4];
    int tid = threadIdx.x;
    int n0 = blockIdx.x * BM;
    int h = blockIdx.y;
    int f0 = h * BN;
    int tx = tid & 7, ty = tid >> 3;
    float acc[8][8];
#pragma unroll
    for (int i = 0; i < 8; i++)
#pragma unroll
        for (int jj = 0; jj < 8; jj++) acc[i][jj] = 0.0f;

    for (int k0 = 0; k0 < IN; k0 += BK) {
        {
            int n = n0 + tid;
#pragma unroll
            for (int i = 0; i < 4; i++) {
                float4 v = (n < N_NODES)
                               ? *(const float4*)&X[(size_t)n * IN + k0 + i * 4]
                               : make_float4(0.f, 0.f, 0.f, 0.f);
                sXT[i * 4 + 0][tid] = v.x;
                sXT[i * 4 + 1][tid] = v.y;
                sXT[i * 4 + 2][tid] = v.z;
                sXT[i * 4 + 3][tid] = v.w;
            }
        }
        {
#pragma unroll
            for (int t = 0; t < 2; t++) {
                int idx = tid + t * 128;
                int kk = idx >> 4, f4 = (idx & 15) * 4;
                *(float4*)&sW[kk][f4] =
                    *(const float4*)&W[((size_t)h * IN + k0 + kk) * 64 + f4];
            }
        }
        __syncthreads();
#pragma unroll
        for (int k = 0; k < BK; k++) {
            float av[8], bv[8];
            *(float4*)(av + 0) = *(const float4*)&sXT[k][ty * 8 + 0];
            *(float4*)(av + 4) = *(const float4*)&sXT[k][ty * 8 + 4];
            *(float4*)(bv + 0) = *(const float4*)&sW[k][tx * 8 + 0];
            *(float4*)(bv + 4) = *(const float4*)&sW[k][tx * 8 + 4];
#pragma unroll
            for (int i = 0; i < 8; i++)
#pragma unroll
                for (int jj = 0; jj < 8; jj++) acc[i][jj] += av[i] * bv[jj];
        }
        __syncthreads();
    }
#pragma unroll
    for (int i = 0; i < 8; i++) {
        int n = n0 + ty * 8 + i;
        if (n < N_NODES) {
            float4 v0 = make_float4(acc[i][0], acc[i][1], acc[i][2], acc[i][3]);
            float4 v1 = make_float4(acc[i][4], acc[i][5], acc[i][6], acc[i][7]);
            *(float4*)&Z[(size_t)n * OUTF + f0 + tx * 8 + 0] = v0;
            *(float4*)&Z[(size_t)n * OUTF + f0 + tx * 8 + 4] = v1;
        }
    }
}

// small GEMM for layer 2: Z[n, o] = sum_d X[n,d] * W2[d,o], OUTF=16
__global__ void __launch_bounds__(256) k_gemm16(const float* __restrict__ X,
                                                const float* __restrict__ W,
                                                float* __restrict__ Z) {
    constexpr int IN = 256, BM = 64, BK = 16;
    __shared__ float sXT[BK][BM + 4];
    __shared__ float sW[BK][16 + 4];
    int tid = threadIdx.x;
    int tx = tid % 16, ty = tid / 16;
    int n0 = blockIdx.x * BM;
    float acc[4] = {0.f, 0.f, 0.f, 0.f};
    for (int k0 = 0; k0 < IN; k0 += BK) {
        {
            int r = tid >> 2, c4 = (tid & 3) * 4;
            int n = n0 + r;
            float4 v = (n < N_NODES)
                           ? *(const float4*)&X[(size_t)n * IN + k0 + c4]
                           : make_float4(0.f, 0.f, 0.f, 0.f);
            sXT[c4 + 0][r] = v.x;
            sXT[c4 + 1][r] = v.y;
            sXT[c4 + 2][r] = v.z;
            sXT[c4 + 3][r] = v.w;
        }
        if (tid < 64) {
            int kk = tid >> 2, f4 = (tid & 3) * 4;
            *(float4*)&sW[kk][f4] = *(const float4*)&W[(size_t)(k0 + kk) * 16 + f4];
        }
        __syncthreads();
#pragma unroll
        for (int k = 0; k < BK; k++) {
            float w = sW[k][tx];
            float4 a = *(const float4*)&sXT[k][ty * 4];
            acc[0] += a.x * w;
            acc[1] += a.y * w;
            acc[2] += a.z * w;
            acc[3] += a.w * w;
        }
        __syncthreads();
    }
#pragma unroll
    for (int i = 0; i < 4; i++) {
        int n = n0 + ty * 4 + i;
        if (n < N_NODES) Z[(size_t)n * 16 + tx] = acc[i];
    }
}

// warp-per-node aggregation over compacted weights (256-wide), float4 gathers,
// 2-unrolled; fused leaky-relu and optional output-row reciprocal norm.
template <bool RELU, bool WRITENORM>
__global__ void k_agg(const float* __restrict__ z, float* __restrict__ out) {
    constexpr int OUTF = 256;
    int n = (blockIdx.x * blockDim.x + threadIdx.x) >> 5;
    if (n >= N_NODES) return;
    int lane = threadIdx.x & 31;
    float ws = g_wself[n];
    float4 acc[2];
    const float4* zn = (const float4*)(z + (size_t)n * OUTF);
#pragma unroll
    for (int i = 0; i < 2; i++) {
        float4 v = zn[lane + 32 * i];
        acc[i] = make_float4(ws * v.x, ws * v.y, ws * v.z, ws * v.w);
    }
    int b = g_rowptr[n], e2 = g_rowend[n];
    int j = b;
    for (; j + 2 <= e2; j += 2) {
        float w0 = g_w[j], w1 = g_w[j + 1];
        int c0 = g_ccol2[j], c1 = g_ccol2[j + 1];
        const float4* z0 = (const float4*)(z + (size_t)c0 * OUTF);
        const float4* z1 = (const float4*)(z + (size_t)c1 * OUTF);
#pragma unroll
        for (int i = 0; i < 2; i++) {
            float4 v0 = z0[lane + 32 * i];
            float4 v1 = z1[lane + 32 * i];
            acc[i].x += w0 * v0.x + w1 * v1.x;
            acc[i].y += w0 * v0.y + w1 * v1.y;
            acc[i].z += w0 * v0.z + w1 * v1.z;
            acc[i].w += w0 * v0.w + w1 * v1.w;
        }
    }
    if (j < e2) {
        float w0 = g_w[j];
        const float4* z0 = (const float4*)(z + (size_t)g_ccol2[j] * OUTF);
#pragma unroll
        for (int i = 0; i < 2; i++) {
            float4 v0 = z0[lane + 32 * i];
            acc[i].x += w0 * v0.x;
            acc[i].y += w0 * v0.y;
            acc[i].z += w0 * v0.z;
            acc[i].w += w0 * v0.w;
        }
    }
    float nrm = 0.0f;
#pragma unroll
    for (int i = 0; i < 2; i++) {
        float4 v = acc[i];
        if (RELU) {
            v.x = (v.x >= 0.f) ? v.x : 0.01f * v.x;
            v.y = (v.y >= 0.f) ? v.y : 0.01f * v.y;
            v.z = (v.z >= 0.f) ? v.z : 0.01f * v.z;
            v.w = (v.w >= 0.f) ? v.w : 0.01f * v.w;
        }
        if (WRITENORM)
            nrm += v.x * v.x + v.y * v.y + v.z * v.z + v.w * v.w;
        ((float4*)(out + (size_t)n * OUTF))[lane + 32 * i] = v;
    }
    if (WRITENORM) {
#pragma unroll
        for (int o = 16; o; o >>= 1) nrm += __shfl_xor_sync(0xffffffffu, nrm, o);
        if (lane == 0) g_rnrm[n] = 1.0f / fmaxf(sqrtf(nrm), 1e-12f);
    }
}

// 16-wide aggregation: two nodes per warp (half-warp each), compacted weights.
__global__ void k_agg16(const float* __restrict__ z, float* __restrict__ out) {
    int w = (blockIdx.x * blockDim.x + threadIdx.x) >> 5;
    int lane = threadIdx.x & 31;
    int n = w * 2 + (lane >> 4);
    if (n >= N_NODES) return;
    int l = lane & 15;
    float acc = g_wself[n] * z[(size_t)n * 16 + l];
    int b = g_rowptr[n], e2 = g_rowend[n];
    int j = b;
    for (; j + 2 <= e2; j += 2) {
        float w0 = g_w[j], w1 = g_w[j + 1];
        int c0 = g_ccol2[j], c1 = g_ccol2[j + 1];
        acc += w0 * z[(size_t)c0 * 16 + l] + w1 * z[(size_t)c1 * 16 + l];
    }
    if (j < e2) acc += g_w[j] * z[(size_t)g_ccol2[j] * 16 + l];
    out[(size_t)n * 16 + l] = acc;
}

// ================= driver ====================================================
extern "C" void kernel_launch(void* const* d_in, const int* in_sizes, int n_in,
                              void* d_out, int out_size) {
    const float* x  = (const float*)d_in[0];
    const float* W0 = (const float*)d_in[1];   // [4,128,64]
    const float* W1 = (const float*)d_in[2];   // [4,256,64]
    const float* W2 = (const float*)d_in[3];   // [1,256,16]
    const int*   row = (const int*)d_in[4];
    const int*   col = (const int*)d_in[5];
    float* out = (float*)d_out;

    float *h1, *h2, *z;
    int* cnt;
    cudaGetSymbolAddress((void**)&h1, g_h1);
    cudaGetSymbolAddress((void**)&h2, g_h2);
    cudaGetSymbolAddress((void**)&z,  g_z);
    cudaGetSymbolAddress((void**)&cnt, g_cnt);

    // side stream + events, created once (host objects only; no device memory)
    static cudaStream_t s1 = nullptr;
    static cudaEvent_t ev[6];
    if (s1 == nullptr) {
        cudaStreamCreateWithFlags(&s1, cudaStreamNonBlocking);
        for (int i = 0; i < 6; i++)
            cudaEventCreateWithFlags(&ev[i], cudaEventDisableTiming);
    }

    const int NODE_WARP_BLOCKS = (N_NODES * 32 + 255) / 256;        // 6250
    const int SIM4_BLOCKS = ((N_EDGES + 3) / 4 * 32 + 255) / 256;   // 25000
    const int SIM2_BLOCKS = ((N_EDGES + 1) / 2 * 32 + 255) / 256;   // 50000
    const int GEMM_MB = (N_NODES + 127) / 128;                      // 391

    // ---- fork: gemm0 (only needs x, W0) runs on s1 under the whole CSR+sim0 --
    cudaEventRecord(ev[0], 0);
    cudaStreamWaitEvent(s1, ev[0], 0);
    k_gemm8<128><<<dim3(GEMM_MB, 4), 128, 0, s1>>>(x, W0, z, 256);

    // ---- s0: CSR build + norms + sim0 + rowdeg0 ----
    cudaMemsetAsync(cnt, 0, N_NODES * sizeof(int), 0);
    k_hist<<<400, 256>>>(row);
    k_scan_fast<<<1, 1024>>>();
    k_scatter<<<400, 256>>>(row, col);
    k_norms<128><<<NODE_WARP_BLOCKS, 256>>>(x);
    k_sim<128, 4><<<SIM4_BLOCKS, 256>>>(x);
    k_rowdeg<<<NODE_WARP_BLOCKS, 256>>>();

    // ---- join, agg0 -> h1 (relu + write next-layer norms) ----
    cudaEventRecord(ev[1], s1);
    cudaStreamWaitEvent(0, ev[1], 0);
    k_agg<true, true><<<NODE_WARP_BLOCKS, 256>>>(z, h1);

    // ---- layer 1: gemm1 on s1  ||  sim1+rowdeg1 on s0 ----
    cudaEventRecord(ev[2], 0);
    cudaStreamWaitEvent(s1, ev[2], 0);
    k_gemm8<256><<<dim3(GEMM_MB, 4), 128, 0, s1>>>(h1, W1, z, 256);
    k_sim<256, 2><<<SIM2_BLOCKS, 256>>>(h1);
    k_rowdeg<<<NODE_WARP_BLOCKS, 256>>>();
    cudaEventRecord(ev[3], s1);
    cudaStreamWaitEvent(0, ev[3], 0);
    k_agg<true, true><<<NODE_WARP_BLOCKS, 256>>>(z, h2);

    // ---- layer 2: gemm2 on s1  ||  sim2+rowdeg2 on s0 ----
    cudaEventRecord(ev[4], 0);
    cudaStreamWaitEvent(s1, ev[4], 0);
    k_gemm16<<<(N_NODES + 63) / 64, 256, 0, s1>>>(h2, W2, z);
    k_sim<256, 2><<<SIM2_BLOCKS, 256>>>(h2);
    k_rowdeg<<<NODE_WARP_BLOCKS, 256>>>();
    cudaEventRecord(ev[5], s1);
    cudaStreamWaitEvent(0, ev[5], 0);
    k_agg16<<<(N_NODES / 2 * 32 + 255) / 256, 256>>>(z, out);
}

// round 13
// speedup vs baseline: 1.5836x; 1.0384x over previous
#include <cuda_runtime.h>
#include <math.h>

#define N_NODES 50000
#define N_EDGES 800000

// ---- scratch (device globals; no allocation allowed) ----
__device__ __align__(16) float g_h1[N_NODES * 256];
__device__ __align__(16) float g_h2[N_NODES * 256];
__device__ __align__(16) float g_z [N_NODES * 256];
__device__ float g_sim[N_EDGES];          // CSR order, raw thresholded sims
__device__ float g_w  [N_EDGES];          // compacted exp-weights
__device__ int   g_ccol[N_EDGES];         // CSR order: col of slot j
__device__ int   g_ccol2[N_EDGES];        // compacted cols
__device__ int   g_crow[N_EDGES];         // CSR order: row of slot j
__device__ float g_rnrm[N_NODES];
__device__ float g_wself[N_NODES];
__device__ int   g_rowptr[N_NODES + 1];
__device__ int   g_rowend[N_NODES];       // end of compacted segment
__device__ int   g_wr[N_NODES];
__device__ int   g_cnt[N_NODES];

// ================= CSR build (row/col fixed across the 3 layers) =============
__global__ void k_hist(const int* __restrict__ row) {
    for (int e = blockIdx.x * blockDim.x + threadIdx.x; e < N_EDGES;
         e += gridDim.x * blockDim.x)
        atomicAdd(&g_cnt[row[e]], 1);
}

// single-block scan, chunk-per-thread: two passes + one block-wide scan
__global__ void __launch_bounds__(1024) k_scan_fast() {
    constexpr int CH = (N_NODES + 1023) / 1024;   // 49
    __shared__ int wsum[32];
    int tid = threadIdx.x, lane = tid & 31, wid = tid >> 5;
    int base = tid * CH;
    int lsum = 0;
#pragma unroll 7
    for (int i = 0; i < CH; i++) {
        int idx = base + i;
        if (idx < N_NODES) lsum += g_cnt[idx];
    }
    int inc = lsum;
#pragma unroll
    for (int o = 1; o < 32; o <<= 1) {
        int y = __shfl_up_sync(0xffffffffu, inc, o);
        if (lane >= o) inc += y;
    }
    if (lane == 31) wsum[wid] = inc;
    __syncthreads();
    if (wid == 0) {
        int w = wsum[lane];
#pragma unroll
        for (int o = 1; o < 32; o <<= 1) {
            int y = __shfl_up_sync(0xffffffffu, w, o);
            if (lane >= o) w += y;
        }
        wsum[lane] = w;
    }
    __syncthreads();
    int excl = (wid ? wsum[wid - 1] : 0) + inc - lsum;
    int run = excl;
#pragma unroll 7
    for (int i = 0; i < CH; i++) {
        int idx = base + i;
        if (idx < N_NODES) {
            g_rowptr[idx] = run;
            g_wr[idx] = run;
            run += g_cnt[idx];
        }
    }
    if (tid == 1023) g_rowptr[N_NODES] = run;
}

__global__ void k_scatter(const int* __restrict__ row, const int* __restrict__ col) {
    for (int e = blockIdx.x * blockDim.x + threadIdx.x; e < N_EDGES;
         e += gridDim.x * blockDim.x) {
        int r = row[e];
        int p = atomicAdd(&g_wr[r], 1);
        g_ccol[p] = col[e];
        g_crow[p] = r;
    }
}

// ================= per-layer kernels =========================================
// reciprocal node norms (raw x only; later layers fold into agg)
template <int IN>
__global__ void k_norms(const float* __restrict__ x) {
    int n = (blockIdx.x * blockDim.x + threadIdx.x) >> 5;
    if (n >= N_NODES) return;
    int lane = threadIdx.x & 31;
    const float4* xr = (const float4*)(x + (size_t)n * IN);
    float s = 0.0f;
#pragma unroll
    for (int i = 0; i < IN / 128; i++) {
        float4 v = xr[lane + 32 * i];
        s += v.x * v.x + v.y * v.y + v.z * v.z + v.w * v.w;
    }
#pragma unroll
    for (int o = 16; o; o >>= 1) s += __shfl_xor_sync(0xffffffffu, s, o);
    if (lane == 0) g_rnrm[n] = 1.0f / fmaxf(sqrtf(s), 1e-12f);
}

// warp-per-U-CSR-slots SDDMM, loads front-batched for MLP.
template <int IN, int U>
__global__ void k_sim(const float* __restrict__ x) {
    int w = (blockIdx.x * blockDim.x + threadIdx.x) >> 5;
    int j0 = w * U;
    if (j0 >= N_EDGES) return;
    int lane = threadIdx.x & 31;
    constexpr int V = IN / 128;
    int rr[U], cc[U];
#pragma unroll
    for (int u = 0; u < U; u++) {
        int j = j0 + u;
        if (j > N_EDGES - 1) j = N_EDGES - 1;
        rr[u] = g_crow[j];
        cc[u] = g_ccol[j];
    }
    float4 a[U][V], b[U][V];
#pragma unroll
    for (int u = 0; u < U; u++) {
        const float4* xa = (const float4*)(x + (size_t)rr[u] * IN);
        const float4* xb = (const float4*)(x + (size_t)cc[u] * IN);
#pragma unroll
        for (int i = 0; i < V; i++) {
            a[u][i] = xa[lane + 32 * i];
            b[u][i] = xb[lane + 32 * i];
        }
    }
    float s[U];
#pragma unroll
    for (int u = 0; u < U; u++) {
        float t = 0.0f;
#pragma unroll
        for (int i = 0; i < V; i++)
            t += a[u][i].x * b[u][i].x + a[u][i].y * b[u][i].y +
                 a[u][i].z * b[u][i].z + a[u][i].w * b[u][i].w;
        s[u] = t;
    }
#pragma unroll
    for (int o = 16; o; o >>= 1)
#pragma unroll
        for (int u = 0; u < U; u++) s[u] += __shfl_xor_sync(0xffffffffu, s[u], o);
    if (lane == 0) {
#pragma unroll
        for (int u = 0; u < U; u++) {
            int j = j0 + u;
            if (j < N_EDGES) {
                float sim = s[u] * g_rnrm[rr[u]] * g_rnrm[cc[u]];
                g_sim[j] = (sim < 0.1f) ? 0.0f : sim;
            }
        }
    }
}

// rowsum + degree + nonzero compaction + exp-weight precompute (warp per node)
__global__ void k_rowdeg() {
    int n = (blockIdx.x * blockDim.x + threadIdx.x) >> 5;
    if (n >= N_NODES) return;
    int lane = threadIdx.x & 31;
    int b = g_rowptr[n], e2 = g_rowptr[n + 1];
    float s = 0.0f;
    int cnt = 0;
    int wpos = b;
    for (int base = b; base < e2; base += 32) {
        int j = base + lane;
        float v = (j < e2) ? g_sim[j] : 0.0f;
        int c = (j < e2) ? g_ccol[j] : 0;
        bool nz = (v != 0.0f);
        unsigned m = __ballot_sync(0xffffffffu, nz);
        int pos = __popc(m & ((1u << lane) - 1u));
        if (nz) {
            g_w[wpos + pos] = v;
            g_ccol2[wpos + pos] = c;
        }
        s += v;
        cnt += nz;
        wpos += __popc(m);
    }
#pragma unroll
    for (int o = 16; o; o >>= 1) {
        s += __shfl_xor_sync(0xffffffffu, s, o);
        cnt += __shfl_xor_sync(0xffffffffu, cnt, o);
    }
    float irs = (s > 0.0f) ? (1.0f / s) : 0.0f;
    for (int j = b + lane; j < wpos; j += 32) g_w[j] = __expf(g_w[j] * irs);
    if (lane == 0) {
        g_rowend[n] = wpos;
        g_wself[n] = __expf(1.0f / (float)(cnt + 1));
    }
}

// ====== 8x8 register-tiled SGEMM, one head per blockIdx.y ======
template <int IN>
__global__ void __launch_bounds__(128) k_gemm8(const float* __restrict__ X,
                                               const float* __restrict__ W,
                                               float* __restrict__ Z,
                                               int OUTF) {
    constexpr int BM = 128, BN = 64, BK = 16;
    __shared__ float sXT[BK][BM + 4];
    __shared__ float sW[BK][BN + 4];
    int tid = threadIdx.x;
    int n0 = blockIdx.x * BM;
    int h = blockIdx.y;
    int f0 = h * BN;
    int tx = tid & 7, ty = tid >> 3;
    float acc[8][8];
#pragma unroll
    for (int i = 0; i < 8; i++)
#pragma unroll
        for (int jj = 0; jj < 8; jj++) acc[i][jj] = 0.0f;

    for (int k0 = 0; k0 < IN; k0 += BK) {
        {
            int n = n0 + tid;
#pragma unroll
            for (int i = 0; i < 4; i++) {
                float4 v = (n < N_NODES)
                               ? *(const float4*)&X[(size_t)n * IN + k0 + i * 4]
                               : make_float4(0.f, 0.f, 0.f, 0.f);
                sXT[i * 4 + 0][tid] = v.x;
                sXT[i * 4 + 1][tid] = v.y;
                sXT[i * 4 + 2][tid] = v.z;
                sXT[i * 4 + 3][tid] = v.w;
            }
        }
        {
#pragma unroll
            for (int t = 0; t < 2; t++) {
                int idx = tid + t * 128;
                int kk = idx >> 4, f4 = (idx & 15) * 4;
                *(float4*)&sW[kk][f4] =
                    *(const float4*)&W[((size_t)h * IN + k0 + kk) * 64 + f4];
            }
        }
        __syncthreads();
#pragma unroll
        for (int k = 0; k < BK; k++) {
            float av[8], bv[8];
            *(float4*)(av + 0) = *(const float4*)&sXT[k][ty * 8 + 0];
            *(float4*)(av + 4) = *(const float4*)&sXT[k][ty * 8 + 4];
            *(float4*)(bv + 0) = *(const float4*)&sW[k][tx * 8 + 0];
            *(float4*)(bv + 4) = *(const float4*)&sW[k][tx * 8 + 4];
#pragma unroll
            for (int i = 0; i < 8; i++)
#pragma unroll
                for (int jj = 0; jj < 8; jj++) acc[i][jj] += av[i] * bv[jj];
        }
        __syncthreads();
    }
#pragma unroll
    for (int i = 0; i < 8; i++) {
        int n = n0 + ty * 8 + i;
        if (n < N_NODES) {
            float4 v0 = make_float4(acc[i][0], acc[i][1], acc[i][2], acc[i][3]);
            float4 v1 = make_float4(acc[i][4], acc[i][5], acc[i][6], acc[i][7]);
            *(float4*)&Z[(size_t)n * OUTF + f0 + tx * 8 + 0] = v0;
            *(float4*)&Z[(size_t)n * OUTF + f0 + tx * 8 + 4] = v1;
        }
    }
}

// small GEMM for layer 2: Z[n, o] = sum_d X[n,d] * W2[d,o], OUTF=16
__global__ void __launch_bounds__(256) k_gemm16(const float* __restrict__ X,
                                                const float* __restrict__ W,
                                                float* __restrict__ Z) {
    constexpr int IN = 256, BM = 64, BK = 16;
    __shared__ float sXT[BK][BM + 4];
    __shared__ float sW[BK][16 + 4];
    int tid = threadIdx.x;
    int tx = tid % 16, ty = tid / 16;
    int n0 = blockIdx.x * BM;
    float acc[4] = {0.f, 0.f, 0.f, 0.f};
    for (int k0 = 0; k0 < IN; k0 += BK) {
        {
            int r = tid >> 2, c4 = (tid & 3) * 4;
            int n = n0 + r;
            float4 v = (n < N_NODES)
                           ? *(const float4*)&X[(size_t)n * IN + k0 + c4]
                           : make_float4(0.f, 0.f, 0.f, 0.f);
            sXT[c4 + 0][r] = v.x;
            sXT[c4 + 1][r] = v.y;
            sXT[c4 + 2][r] = v.z;
            sXT[c4 + 3][r] = v.w;
        }
        if (tid < 64) {
            int kk = tid >> 2, f4 = (tid & 3) * 4;
            *(float4*)&sW[kk][f4] = *(const float4*)&W[(size_t)(k0 + kk) * 16 + f4];
        }
        __syncthreads();
#pragma unroll
        for (int k = 0; k < BK; k++) {
            float w = sW[k][tx];
            float4 a = *(const float4*)&sXT[k][ty * 4];
            acc[0] += a.x * w;
            acc[1] += a.y * w;
            acc[2] += a.z * w;
            acc[3] += a.w * w;
        }
        __syncthreads();
    }
#pragma unroll
    for (int i = 0; i < 4; i++) {
        int n = n0 + ty * 4 + i;
        if (n < N_NODES) Z[(size_t)n * 16 + tx] = acc[i];
    }
}

// warp-per-node aggregation over compacted weights (256-wide), float4 gathers,
// 4-edge unrolled for MLP; fused leaky-relu and optional output-row norm.
template <bool RELU, bool WRITENORM>
__global__ void k_agg(const float* __restrict__ z, float* __restrict__ out) {
    constexpr int OUTF = 256;
    int n = (blockIdx.x * blockDim.x + threadIdx.x) >> 5;
    if (n >= N_NODES) return;
    int lane = threadIdx.x & 31;
    float ws = g_wself[n];
    float4 acc[2];
    const float4* zn = (const float4*)(z + (size_t)n * OUTF);
#pragma unroll
    for (int i = 0; i < 2; i++) {
        float4 v = zn[lane + 32 * i];
        acc[i] = make_float4(ws * v.x, ws * v.y, ws * v.z, ws * v.w);
    }
    int b = g_rowptr[n], e2 = g_rowend[n];
    int j = b;
    for (; j + 4 <= e2; j += 4) {
        float w0 = g_w[j], w1 = g_w[j + 1], w2 = g_w[j + 2], w3 = g_w[j + 3];
        int c0 = g_ccol2[j], c1 = g_ccol2[j + 1], c2 = g_ccol2[j + 2], c3 = g_ccol2[j + 3];
        const float4* z0 = (const float4*)(z + (size_t)c0 * OUTF);
        const float4* z1 = (const float4*)(z + (size_t)c1 * OUTF);
        const float4* z2 = (const float4*)(z + (size_t)c2 * OUTF);
        const float4* z3 = (const float4*)(z + (size_t)c3 * OUTF);
#pragma unroll
        for (int i = 0; i < 2; i++) {
            float4 v0 = z0[lane + 32 * i];
            float4 v1 = z1[lane + 32 * i];
            float4 v2 = z2[lane + 32 * i];
            float4 v3 = z3[lane + 32 * i];
            acc[i].x += w0 * v0.x + w1 * v1.x + w2 * v2.x + w3 * v3.x;
            acc[i].y += w0 * v0.y + w1 * v1.y + w2 * v2.y + w3 * v3.y;
            acc[i].z += w0 * v0.z + w1 * v1.z + w2 * v2.z + w3 * v3.z;
            acc[i].w += w0 * v0.w + w1 * v1.w + w2 * v2.w + w3 * v3.w;
        }
    }
    for (; j < e2; j++) {
        float w0 = g_w[j];
        const float4* z0 = (const float4*)(z + (size_t)g_ccol2[j] * OUTF);
#pragma unroll
        for (int i = 0; i < 2; i++) {
            float4 v0 = z0[lane + 32 * i];
            acc[i].x += w0 * v0.x;
            acc[i].y += w0 * v0.y;
            acc[i].z += w0 * v0.z;
            acc[i].w += w0 * v0.w;
        }
    }
    float nrm = 0.0f;
#pragma unroll
    for (int i = 0; i < 2; i++) {
        float4 v = acc[i];
        if (RELU) {
            v.x = (v.x >= 0.f) ? v.x : 0.01f * v.x;
            v.y = (v.y >= 0.f) ? v.y : 0.01f * v.y;
            v.z = (v.z >= 0.f) ? v.z : 0.01f * v.z;
            v.w = (v.w >= 0.f) ? v.w : 0.01f * v.w;
        }
        if (WRITENORM)
            nrm += v.x * v.x + v.y * v.y + v.z * v.z + v.w * v.w;
        ((float4*)(out + (size_t)n * OUTF))[lane + 32 * i] = v;
    }
    if (WRITENORM) {
#pragma unroll
        for (int o = 16; o; o >>= 1) nrm += __shfl_xor_sync(0xffffffffu, nrm, o);
        if (lane == 0) g_rnrm[n] = 1.0f / fmaxf(sqrtf(nrm), 1e-12f);
    }
}

// 16-wide aggregation: two nodes per warp (half-warp each), 4-edge unrolled.
__global__ void k_agg16(const float* __restrict__ z, float* __restrict__ out) {
    int w = (blockIdx.x * blockDim.x + threadIdx.x) >> 5;
    int lane = threadIdx.x & 31;
    int n = w * 2 + (lane >> 4);
    if (n >= N_NODES) return;
    int l = lane & 15;
    float acc = g_wself[n] * z[(size_t)n * 16 + l];
    int b = g_rowptr[n], e2 = g_rowend[n];
    int j = b;
    for (; j + 4 <= e2; j += 4) {
        float w0 = g_w[j], w1 = g_w[j + 1], w2 = g_w[j + 2], w3 = g_w[j + 3];
        int c0 = g_ccol2[j], c1 = g_ccol2[j + 1], c2 = g_ccol2[j + 2], c3 = g_ccol2[j + 3];
        acc += w0 * z[(size_t)c0 * 16 + l] + w1 * z[(size_t)c1 * 16 + l] +
               w2 * z[(size_t)c2 * 16 + l] + w3 * z[(size_t)c3 * 16 + l];
    }
    for (; j < e2; j++) acc += g_w[j] * z[(size_t)g_ccol2[j] * 16 + l];
    out[(size_t)n * 16 + l] = acc;
}

// ================= driver ====================================================
extern "C" void kernel_launch(void* const* d_in, const int* in_sizes, int n_in,
                              void* d_out, int out_size) {
    const float* x  = (const float*)d_in[0];
    const float* W0 = (const float*)d_in[1];   // [4,128,64]
    const float* W1 = (const float*)d_in[2];   // [4,256,64]
    const float* W2 = (const float*)d_in[3];   // [1,256,16]
    const int*   row = (const int*)d_in[4];
    const int*   col = (const int*)d_in[5];
    float* out = (float*)d_out;

    float *h1, *h2, *z;
    int* cnt;
    cudaGetSymbolAddress((void**)&h1, g_h1);
    cudaGetSymbolAddress((void**)&h2, g_h2);
    cudaGetSymbolAddress((void**)&z,  g_z);
    cudaGetSymbolAddress((void**)&cnt, g_cnt);

    // side stream + events, created once (host objects only; no device memory)
    static cudaStream_t s1 = nullptr;
    static cudaEvent_t ev[6];
    if (s1 == nullptr) {
        cudaStreamCreateWithFlags(&s1, cudaStreamNonBlocking);
        for (int i = 0; i < 6; i++)
            cudaEventCreateWithFlags(&ev[i], cudaEventDisableTiming);
    }

    const int NODE_WARP_BLOCKS = (N_NODES * 32 + 255) / 256;        // 6250
    const int SIM4_BLOCKS = ((N_EDGES + 3) / 4 * 32 + 255) / 256;   // 25000
    const int GEMM_MB = (N_NODES + 127) / 128;                      // 391

    // ---- fork: gemm0 (only needs x, W0) runs on s1 under the whole CSR+sim0 --
    cudaEventRecord(ev[0], 0);
    cudaStreamWaitEvent(s1, ev[0], 0);
    k_gemm8<128><<<dim3(GEMM_MB, 4), 128, 0, s1>>>(x, W0, z, 256);

    // ---- s0: CSR build + norms + sim0 + rowdeg0 ----
    cudaMemsetAsync(cnt, 0, N_NODES * sizeof(int), 0);
    k_hist<<<400, 256>>>(row);
    k_scan_fast<<<1, 1024>>>();
    k_scatter<<<400, 256>>>(row, col);
    k_norms<128><<<NODE_WARP_BLOCKS, 256>>>(x);
    k_sim<128, 4><<<SIM4_BLOCKS, 256>>>(x);
    k_rowdeg<<<NODE_WARP_BLOCKS, 256>>>();

    // ---- join, agg0 -> h1 (relu + write next-layer norms) ----
    cudaEventRecord(ev[1], s1);
    cudaStreamWaitEvent(0, ev[1], 0);
    k_agg<true, true><<<NODE_WARP_BLOCKS, 256>>>(z, h1);

    // ---- layer 1: gemm1 on s1  ||  sim1+rowdeg1 on s0 ----
    cudaEventRecord(ev[2], 0);
    cudaStreamWaitEvent(s1, ev[2], 0);
    k_gemm8<256><<<dim3(GEMM_MB, 4), 128, 0, s1>>>(h1, W1, z, 256);
    k_sim<256, 4><<<SIM4_BLOCKS, 256>>>(h1);
    k_rowdeg<<<NODE_WARP_BLOCKS, 256>>>();
    cudaEventRecord(ev[3], s1);
    cudaStreamWaitEvent(0, ev[3], 0);
    k_agg<true, true><<<NODE_WARP_BLOCKS, 256>>>(z, h2);

    // ---- layer 2: gemm2 on s1  ||  sim2+rowdeg2 on s0 ----
    cudaEventRecord(ev[4], 0);
    cudaStreamWaitEvent(s1, ev[4], 0);
    k_gemm16<<<(N_NODES + 63) / 64, 256, 0, s1>>>(h2, W2, z);
    k_sim<256, 4><<<SIM4_BLOCKS, 256>>>(h2);
    k_rowdeg<<<NODE_WARP_BLOCKS, 256>>>();
    cudaEventRecord(ev[5], s1);
    cudaStreamWaitEvent(0, ev[5], 0);
    k_agg16<<<(N_NODES / 2 * 32 + 255) / 256, 256>>>(z, out);
}

// round 15
// speedup vs baseline: 1.5984x; 1.0093x over previous
#include <cuda_runtime.h>
#include <math.h>

#define N_NODES 50000
#define N_EDGES 800000

// ---- scratch (device globals; no allocation allowed) ----
__device__ __align__(16) float g_h1[N_NODES * 256];
__device__ __align__(16) float g_h2[N_NODES * 256];
__device__ __align__(16) float g_z [N_NODES * 256];
__device__ float g_sim[N_EDGES];          // CSR order, raw thresholded sims
__device__ float g_w  [N_EDGES];          // compacted exp-weights (layer 1)
__device__ int   g_ccol[N_EDGES];         // CSR order: col of slot j
__device__ int   g_ccol2[N_EDGES];        // compacted cols (layer 1)
__device__ int   g_crow[N_EDGES];         // CSR order: row of slot j
__device__ float g_rnrm[N_NODES];
__device__ float g_wself[N_NODES];
__device__ int   g_rowptr[N_NODES + 1];
__device__ int   g_rowend[N_NODES];       // end of compacted segment (layer 1)
__device__ int   g_wr[N_NODES];
__device__ int   g_cnt[N_NODES];

// ================= CSR build (row/col fixed across the 3 layers) =============
__global__ void k_hist(const int* __restrict__ row) {
    for (int e = blockIdx.x * blockDim.x + threadIdx.x; e < N_EDGES;
         e += gridDim.x * blockDim.x)
        atomicAdd(&g_cnt[row[e]], 1);
}

// single-block scan, chunk-per-thread: two passes + one block-wide scan
__global__ void __launch_bounds__(1024) k_scan_fast() {
    constexpr int CH = (N_NODES + 1023) / 1024;   // 49
    __shared__ int wsum[32];
    int tid = threadIdx.x, lane = tid & 31, wid = tid >> 5;
    int base = tid * CH;
    int lsum = 0;
#pragma unroll 7
    for (int i = 0; i < CH; i++) {
        int idx = base + i;
        if (idx < N_NODES) lsum += g_cnt[idx];
    }
    int inc = lsum;
#pragma unroll
    for (int o = 1; o < 32; o <<= 1) {
        int y = __shfl_up_sync(0xffffffffu, inc, o);
        if (lane >= o) inc += y;
    }
    if (lane == 31) wsum[wid] = inc;
    __syncthreads();
    if (wid == 0) {
        int w = wsum[lane];
#pragma unroll
        for (int o = 1; o < 32; o <<= 1) {
            int y = __shfl_up_sync(0xffffffffu, w, o);
            if (lane >= o) w += y;
        }
        wsum[lane] = w;
    }
    __syncthreads();
    int excl = (wid ? wsum[wid - 1] : 0) + inc - lsum;
    int run = excl;
#pragma unroll 7
    for (int i = 0; i < CH; i++) {
        int idx = base + i;
        if (idx < N_NODES) {
            g_rowptr[idx] = run;
            g_wr[idx] = run;
            run += g_cnt[idx];
        }
    }
    if (tid == 1023) g_rowptr[N_NODES] = run;
}

__global__ void k_scatter(const int* __restrict__ row, const int* __restrict__ col) {
    for (int e = blockIdx.x * blockDim.x + threadIdx.x; e < N_EDGES;
         e += gridDim.x * blockDim.x) {
        int r = row[e];
        int p = atomicAdd(&g_wr[r], 1);
        g_ccol[p] = col[e];
        g_crow[p] = r;
    }
}

// ================= per-layer kernels =========================================
// reciprocal node norms (raw x only; later layers fold into agg)
template <int IN>
__global__ void k_norms(const float* __restrict__ x) {
    int n = (blockIdx.x * blockDim.x + threadIdx.x) >> 5;
    if (n >= N_NODES) return;
    int lane = threadIdx.x & 31;
    const float4* xr = (const float4*)(x + (size_t)n * IN);
    float s = 0.0f;
#pragma unroll
    for (int i = 0; i < IN / 128; i++) {
        float4 v = xr[lane + 32 * i];
        s += v.x * v.x + v.y * v.y + v.z * v.z + v.w * v.w;
    }
#pragma unroll
    for (int o = 16; o; o >>= 1) s += __shfl_xor_sync(0xffffffffu, s, o);
    if (lane == 0) g_rnrm[n] = 1.0f / fmaxf(sqrtf(s), 1e-12f);
}

// warp-per-U-CSR-slots SDDMM, loads front-batched for MLP.
template <int IN, int U>
__global__ void k_sim(const float* __restrict__ x) {
    int w = (blockIdx.x * blockDim.x + threadIdx.x) >> 5;
    int j0 = w * U;
    if (j0 >= N_EDGES) return;
    int lane = threadIdx.x & 31;
    constexpr int V = IN / 128;
    int rr[U], cc[U];
#pragma unroll
    for (int u = 0; u < U; u++) {
        int j = j0 + u;
        if (j > N_EDGES - 1) j = N_EDGES - 1;
        rr[u] = g_crow[j];
        cc[u] = g_ccol[j];
    }
    float4 a[U][V], b[U][V];
#pragma unroll
    for (int u = 0; u < U; u++) {
        const float4* xa = (const float4*)(x + (size_t)rr[u] * IN);
        const float4* xb = (const float4*)(x + (size_t)cc[u] * IN);
#pragma unroll
        for (int i = 0; i < V; i++) {
            a[u][i] = xa[lane + 32 * i];
            b[u][i] = xb[lane + 32 * i];
        }
    }
    float s[U];
#pragma unroll
    for (int u = 0; u < U; u++) {
        float t = 0.0f;
#pragma unroll
        for (int i = 0; i < V; i++)
            t += a[u][i].x * b[u][i].x + a[u][i].y * b[u][i].y +
                 a[u][i].z * b[u][i].z + a[u][i].w * b[u][i].w;
        s[u] = t;
    }
#pragma unroll
    for (int o = 16; o; o >>= 1)
#pragma unroll
        for (int u = 0; u < U; u++) s[u] += __shfl_xor_sync(0xffffffffu, s[u], o);
    if (lane == 0) {
#pragma unroll
        for (int u = 0; u < U; u++) {
            int j = j0 + u;
            if (j < N_EDGES) {
                float sim = s[u] * g_rnrm[rr[u]] * g_rnrm[cc[u]];
                g_sim[j] = (sim < 0.1f) ? 0.0f : sim;
            }
        }
    }
}

// rowsum + degree + nonzero compaction + exp-weight precompute (layer 1 only;
// runs hidden under gemm1)
__global__ void k_rowdeg() {
    int n = (blockIdx.x * blockDim.x + threadIdx.x) >> 5;
    if (n >= N_NODES) return;
    int lane = threadIdx.x & 31;
    int b = g_rowptr[n], e2 = g_rowptr[n + 1];
    float s = 0.0f;
    int cnt = 0;
    int wpos = b;
    for (int base = b; base < e2; base += 32) {
        int j = base + lane;
        float v = (j < e2) ? g_sim[j] : 0.0f;
        int c = (j < e2) ? g_ccol[j] : 0;
        bool nz = (v != 0.0f);
        unsigned m = __ballot_sync(0xffffffffu, nz);
        int pos = __popc(m & ((1u << lane) - 1u));
        if (nz) {
            g_w[wpos + pos] = v;
            g_ccol2[wpos + pos] = c;
        }
        s += v;
        cnt += nz;
        wpos += __popc(m);
    }
#pragma unroll
    for (int o = 16; o; o >>= 1) {
        s += __shfl_xor_sync(0xffffffffu, s, o);
        cnt += __shfl_xor_sync(0xffffffffu, cnt, o);
    }
    float irs = (s > 0.0f) ? (1.0f / s) : 0.0f;
    for (int j = b + lane; j < wpos; j += 32) g_w[j] = __expf(g_w[j] * irs);
    if (lane == 0) {
        g_rowend[n] = wpos;
        g_wself[n] = __expf(1.0f / (float)(cnt + 1));
    }
}

// ====== 8x8 register-tiled SGEMM, one head per blockIdx.y ======
template <int IN>
__global__ void __launch_bounds__(128) k_gemm8(const float* __restrict__ X,
                                               const float* __restrict__ W,
                                               float* __restrict__ Z,
                                               int OUTF) {
    constexpr int BM = 128, BN = 64, BK = 16;
    __shared__ float sXT[BK][BM + 4];
    __shared__ float sW[BK][BN + 4];
    int tid = threadIdx.x;
    int n0 = blockIdx.x * BM;
    int h = blockIdx.y;
    int f0 = h * BN;
    int tx = tid & 7, ty = tid >> 3;
    float acc[8][8];
#pragma unroll
    for (int i = 0; i < 8; i++)
#pragma unroll
        for (int jj = 0; jj < 8; jj++) acc[i][jj] = 0.0f;

    for (int k0 = 0; k0 < IN; k0 += BK) {
        {
            int n = n0 + tid;
#pragma unroll
            for (int i = 0; i < 4; i++) {
                float4 v = (n < N_NODES)
                               ? *(const float4*)&X[(size_t)n * IN + k0 + i * 4]
                               : make_float4(0.f, 0.f, 0.f, 0.f);
                sXT[i * 4 + 0][tid] = v.x;
                sXT[i * 4 + 1][tid] = v.y;
                sXT[i * 4 + 2][tid] = v.z;
                sXT[i * 4 + 3][tid] = v.w;
            }
        }
        {
#pragma unroll
            for (int t = 0; t < 2; t++) {
                int idx = tid + t * 128;
                int kk = idx >> 4, f4 = (idx & 15) * 4;
                *(float4*)&sW[kk][f4] =
                    *(const float4*)&W[((size_t)h * IN + k0 + kk) * 64 + f4];
            }
        }
        __syncthreads();
#pragma unroll
        for (int k = 0; k < BK; k++) {
            float av[8], bv[8];
            *(float4*)(av + 0) = *(const float4*)&sXT[k][ty * 8 + 0];
            *(float4*)(av + 4) = *(const float4*)&sXT[k][ty * 8 + 4];
            *(float4*)(bv + 0) = *(const float4*)&sW[k][tx * 8 + 0];
            *(float4*)(bv + 4) = *(const float4*)&sW[k][tx * 8 + 4];
#pragma unroll
            for (int i = 0; i < 8; i++)
#pragma unroll
                for (int jj = 0; jj < 8; jj++) acc[i][jj] += av[i] * bv[jj];
        }
        __syncthreads();
    }
#pragma unroll
    for (int i = 0; i < 8; i++) {
        int n = n0 + ty * 8 + i;
        if (n < N_NODES) {
            float4 v0 = make_float4(acc[i][0], acc[i][1], acc[i][2], acc[i][3]);
            float4 v1 = make_float4(acc[i][4], acc[i][5], acc[i][6], acc[i][7]);
            *(float4*)&Z[(size_t)n * OUTF + f0 + tx * 8 + 0] = v0;
            *(float4*)&Z[(size_t)n * OUTF + f0 + tx * 8 + 4] = v1;
        }
    }
}

// small GEMM for layer 2: Z[n, o] = sum_d X[n,d] * W2[d,o], OUTF=16
__global__ void __launch_bounds__(256) k_gemm16(const float* __restrict__ X,
                                                const float* __restrict__ W,
                                                float* __restrict__ Z) {
    constexpr int IN = 256, BM = 64, BK = 16;
    __shared__ float sXT[BK][BM + 4];
    __shared__ float sW[BK][16 + 4];
    int tid = threadIdx.x;
    int tx = tid % 16, ty = tid / 16;
    int n0 = blockIdx.x * BM;
    float acc[4] = {0.f, 0.f, 0.f, 0.f};
    for (int k0 = 0; k0 < IN; k0 += BK) {
        {
            int r = tid >> 2, c4 = (tid & 3) * 4;
            int n = n0 + r;
            float4 v = (n < N_NODES)
                           ? *(const float4*)&X[(size_t)n * IN + k0 + c4]
                           : make_float4(0.f, 0.f, 0.f, 0.f);
            sXT[c4 + 0][r] = v.x;
            sXT[c4 + 1][r] = v.y;
            sXT[c4 + 2][r] = v.z;
            sXT[c4 + 3][r] = v.w;
        }
        if (tid < 64) {
            int kk = tid >> 2, f4 = (tid & 3) * 4;
            *(float4*)&sW[kk][f4] = *(const float4*)&W[(size_t)(k0 + kk) * 16 + f4];
        }
        __syncthreads();
#pragma unroll
        for (int k = 0; k < BK; k++) {
            float w = sW[k][tx];
            float4 a = *(const float4*)&sXT[k][ty * 4];
            acc[0] += a.x * w;
            acc[1] += a.y * w;
            acc[2] += a.z * w;
            acc[3] += a.w * w;
        }
        __syncthreads();
    }
#pragma unroll
    for (int i = 0; i < 4; i++) {
        int n = n0 + ty * 4 + i;
        if (n < N_NODES) Z[(size_t)n * 16 + tx] = acc[i];
    }
}

// ====== FUSED agg (layers 0/2-256wide): rowsum+deg+compaction-to-smem + gather
template <bool RELU, bool WRITENORM>
__global__ void __launch_bounds__(256) k_aggf(const float* __restrict__ z,
                                              float* __restrict__ out) {
    constexpr int OUTF = 256;
    constexpr int CAP = 128;
    __shared__ float sw[8][CAP];
    __shared__ int   sc[8][CAP];
    int wl = threadIdx.x >> 5;
    int n = (blockIdx.x * blockDim.x + threadIdx.x) >> 5;
    if (n >= N_NODES) return;
    int lane = threadIdx.x & 31;
    int b = g_rowptr[n], e2 = g_rowptr[n + 1];

    // pass 1: rowsum + count + compact nonzeros into smem
    float s = 0.0f;
    int cnt = 0;
    int np = 0;
    for (int base = b; base < e2; base += 32) {
        int j = base + lane;
        float v = (j < e2) ? g_sim[j] : 0.0f;
        int c = (j < e2) ? g_ccol[j] : 0;
        bool nz = (v != 0.0f);
        unsigned m = __ballot_sync(0xffffffffu, nz);
        int pos = np + __popc(m & ((1u << lane) - 1u));
        if (nz && pos < CAP) { sw[wl][pos] = v; sc[wl][pos] = c; }
        s += v;
        cnt += nz;
        np += __popc(m);
    }
#pragma unroll
    for (int o = 16; o; o >>= 1) {
        s += __shfl_xor_sync(0xffffffffu, s, o);
        cnt += __shfl_xor_sync(0xffffffffu, cnt, o);
    }
    float irs = (s > 0.0f) ? (1.0f / s) : 0.0f;
    float ws = __expf(1.0f / (float)(cnt + 1));
    if (WRITENORM && lane == 0) g_wself[n] = 0.0f;   // unused; keep regs simple

    // accumulator init with self term
    float4 acc[2];
    const float4* zn = (const float4*)(z + (size_t)n * OUTF);
#pragma unroll
    for (int i = 0; i < 2; i++) {
        float4 v = zn[lane + 32 * i];
        acc[i] = make_float4(ws * v.x, ws * v.y, ws * v.z, ws * v.w);
    }

    if (np <= CAP) {
        // convert sims to weights in smem
        for (int j = lane; j < np; j += 32) sw[wl][j] = __expf(sw[wl][j] * irs);
        __syncwarp();
        int j = 0;
        for (; j + 4 <= np; j += 4) {
            float w0 = sw[wl][j], w1 = sw[wl][j + 1], w2 = sw[wl][j + 2], w3 = sw[wl][j + 3];
            int c0 = sc[wl][j], c1 = sc[wl][j + 1], c2 = sc[wl][j + 2], c3 = sc[wl][j + 3];
            const float4* z0 = (const float4*)(z + (size_t)c0 * OUTF);
            const float4* z1 = (const float4*)(z + (size_t)c1 * OUTF);
            const float4* z2 = (const float4*)(z + (size_t)c2 * OUTF);
            const float4* z3 = (const float4*)(z + (size_t)c3 * OUTF);
#pragma unroll
            for (int i = 0; i < 2; i++) {
                float4 v0 = z0[lane + 32 * i];
                float4 v1 = z1[lane + 32 * i];
                float4 v2 = z2[lane + 32 * i];
                float4 v3 = z3[lane + 32 * i];
                acc[i].x += w0 * v0.x + w1 * v1.x + w2 * v2.x + w3 * v3.x;
                acc[i].y += w0 * v0.y + w1 * v1.y + w2 * v2.y + w3 * v3.y;
                acc[i].z += w0 * v0.z + w1 * v1.z + w2 * v2.z + w3 * v3.z;
                acc[i].w += w0 * v0.w + w1 * v1.w + w2 * v2.w + w3 * v3.w;
            }
        }
        for (; j < np; j++) {
            float w0 = sw[wl][j];
            const float4* z0 = (const float4*)(z + (size_t)sc[wl][j] * OUTF);
#pragma unroll
            for (int i = 0; i < 2; i++) {
                float4 v0 = z0[lane + 32 * i];
                acc[i].x += w0 * v0.x;
                acc[i].y += w0 * v0.y;
                acc[i].z += w0 * v0.z;
                acc[i].w += w0 * v0.w;
            }
        }
    } else {
        // overflow fallback (deg > CAP): branchy loop over globals
        for (int j = b; j < e2; j++) {
            float v = g_sim[j];
            if (v != 0.0f) {
                float w0 = __expf(v * irs);
                const float4* z0 = (const float4*)(z + (size_t)g_ccol[j] * OUTF);
#pragma unroll
                for (int i = 0; i < 2; i++) {
                    float4 v0 = z0[lane + 32 * i];
                    acc[i].x += w0 * v0.x;
                    acc[i].y += w0 * v0.y;
                    acc[i].z += w0 * v0.z;
                    acc[i].w += w0 * v0.w;
                }
            }
        }
    }

    float nrm = 0.0f;
#pragma unroll
    for (int i = 0; i < 2; i++) {
        float4 v = acc[i];
        if (RELU) {
            v.x = (v.x >= 0.f) ? v.x : 0.01f * v.x;
            v.y = (v.y >= 0.f) ? v.y : 0.01f * v.y;
            v.z = (v.z >= 0.f) ? v.z : 0.01f * v.z;
            v.w = (v.w >= 0.f) ? v.w : 0.01f * v.w;
        }
        if (WRITENORM)
            nrm += v.x * v.x + v.y * v.y + v.z * v.z + v.w * v.w;
        ((float4*)(out + (size_t)n * OUTF))[lane + 32 * i] = v;
    }
    if (WRITENORM) {
#pragma unroll
        for (int o = 16; o; o >>= 1) nrm += __shfl_xor_sync(0xffffffffu, nrm, o);
        if (lane == 0) g_rnrm[n] = 1.0f / fmaxf(sqrtf(nrm), 1e-12f);
    }
}

// compacted agg (layer 1; weights precomputed by hidden k_rowdeg)
template <bool RELU, bool WRITENORM>
__global__ void k_agg(const float* __restrict__ z, float* __restrict__ out) {
    constexpr int OUTF = 256;
    int n = (blockIdx.x * blockDim.x + threadIdx.x) >> 5;
    if (n >= N_NODES) return;
    int lane = threadIdx.x & 31;
    float ws = g_wself[n];
    float4 acc[2];
    const float4* zn = (const float4*)(z + (size_t)n * OUTF);
#pragma unroll
    for (int i = 0; i < 2; i++) {
        float4 v = zn[lane + 32 * i];
        acc[i] = make_float4(ws * v.x, ws * v.y, ws * v.z, ws * v.w);
    }
    int b = g_rowptr[n], e2 = g_rowend[n];
    int j = b;
    for (; j + 4 <= e2; j += 4) {
        float w0 = g_w[j], w1 = g_w[j + 1], w2 = g_w[j + 2], w3 = g_w[j + 3];
        int c0 = g_ccol2[j], c1 = g_ccol2[j + 1], c2 = g_ccol2[j + 2], c3 = g_ccol2[j + 3];
        const float4* z0 = (const float4*)(z + (size_t)c0 * OUTF);
        const float4* z1 = (const float4*)(z + (size_t)c1 * OUTF);
        const float4* z2 = (const float4*)(z + (size_t)c2 * OUTF);
        const float4* z3 = (const float4*)(z + (size_t)c3 * OUTF);
#pragma unroll
        for (int i = 0; i < 2; i++) {
            float4 v0 = z0[lane + 32 * i];
            float4 v1 = z1[lane + 32 * i];
            float4 v2 = z2[lane + 32 * i];
            float4 v3 = z3[lane + 32 * i];
            acc[i].x += w0 * v0.x + w1 * v1.x + w2 * v2.x + w3 * v3.x;
            acc[i].y += w0 * v0.y + w1 * v1.y + w2 * v2.y + w3 * v3.y;
            acc[i].z += w0 * v0.z + w1 * v1.z + w2 * v2.z + w3 * v3.z;
            acc[i].w += w0 * v0.w + w1 * v1.w + w2 * v2.w + w3 * v3.w;
        }
    }
    for (; j < e2; j++) {
        float w0 = g_w[j];
        const float4* z0 = (const float4*)(z + (size_t)g_ccol2[j] * OUTF);
#pragma unroll
        for (int i = 0; i < 2; i++) {
            float4 v0 = z0[lane + 32 * i];
            acc[i].x += w0 * v0.x;
            acc[i].y += w0 * v0.y;
            acc[i].z += w0 * v0.z;
            acc[i].w += w0 * v0.w;
        }
    }
    float nrm = 0.0f;
#pragma unroll
    for (int i = 0; i < 2; i++) {
        float4 v = acc[i];
        if (RELU) {
            v.x = (v.x >= 0.f) ? v.x : 0.01f * v.x;
            v.y = (v.y >= 0.f) ? v.y : 0.01f * v.y;
            v.z = (v.z >= 0.f) ? v.z : 0.01f * v.z;
            v.w = (v.w >= 0.f) ? v.w : 0.01f * v.w;
        }
        if (WRITENORM)
            nrm += v.x * v.x + v.y * v.y + v.z * v.z + v.w * v.w;
        ((float4*)(out + (size_t)n * OUTF))[lane + 32 * i] = v;
    }
    if (WRITENORM) {
#pragma unroll
        for (int o = 16; o; o >>= 1) nrm += __shfl_xor_sync(0xffffffffu, nrm, o);
        if (lane == 0) g_rnrm[n] = 1.0f / fmaxf(sqrtf(nrm), 1e-12f);
    }
}

// FUSED 16-wide aggregation (layer 2): warp per node, pass1 rowsum/deg then
// paired-edge branchy gather (z16 rows are only 64B; skips are cheap).
__global__ void k_agg16f(const float* __restrict__ z, float* __restrict__ out) {
    int n = (blockIdx.x * blockDim.x + threadIdx.x) >> 5;
    if (n >= N_NODES) return;
    int lane = threadIdx.x & 31;
    int b = g_rowptr[n], e2 = g_rowptr[n + 1];

    // pass 1: rowsum + count
    float s = 0.0f;
    int cnt = 0;
    for (int j = b + lane; j < e2; j += 32) {
        float v = g_sim[j];
        s += v;
        cnt += (v != 0.0f);
    }
#pragma unroll
    for (int o = 16; o; o >>= 1) {
        s += __shfl_xor_sync(0xffffffffu, s, o);
        cnt += __shfl_xor_sync(0xffffffffu, cnt, o);
    }
    float irs = (s > 0.0f) ? (1.0f / s) : 0.0f;
    float ws = __expf(1.0f / (float)(cnt + 1));

    // pass 2: halves of the warp process alternating edges
    int l = lane & 15;
    float acc = 0.0f;
    for (int j = b + (lane >> 4); j < e2; j += 2) {
        float v = g_sim[j];
        if (v != 0.0f)
            acc += __expf(v * irs) * z[(size_t)g_ccol[j] * 16 + l];
    }
    acc += __shfl_down_sync(0xffffffffu, acc, 16);
    if (lane < 16)
        out[(size_t)n * 16 + l] = ws * z[(size_t)n * 16 + l] + acc;
}

// ================= driver ====================================================
extern "C" void kernel_launch(void* const* d_in, const int* in_sizes, int n_in,
                              void* d_out, int out_size) {
    const float* x  = (const float*)d_in[0];
    const float* W0 = (const float*)d_in[1];   // [4,128,64]
    const float* W1 = (const float*)d_in[2];   // [4,256,64]
    const float* W2 = (const float*)d_in[3];   // [1,256,16]
    const int*   row = (const int*)d_in[4];
    const int*   col = (const int*)d_in[5];
    float* out = (float*)d_out;

    float *h1, *h2, *z;
    int* cnt;
    cudaGetSymbolAddress((void**)&h1, g_h1);
    cudaGetSymbolAddress((void**)&h2, g_h2);
    cudaGetSymbolAddress((void**)&z,  g_z);
    cudaGetSymbolAddress((void**)&cnt, g_cnt);

    // side stream + events, created once (host objects only; no device memory)
    static cudaStream_t s1 = nullptr;
    static cudaEvent_t ev[6];
    if (s1 == nullptr) {
        cudaStreamCreateWithFlags(&s1, cudaStreamNonBlocking);
        for (int i = 0; i < 6; i++)
            cudaEventCreateWithFlags(&ev[i], cudaEventDisableTiming);
    }

    const int NODE_WARP_BLOCKS = (N_NODES * 32 + 255) / 256;        // 6250
    const int SIM4_BLOCKS = ((N_EDGES + 3) / 4 * 32 + 255) / 256;   // 25000
    const int GEMM_MB = (N_NODES + 127) / 128;                      // 391

    // ---- fork: gemm0 (only needs x, W0) runs on s1 under the whole CSR+sim0 --
    cudaEventRecord(ev[0], 0);
    cudaStreamWaitEvent(s1, ev[0], 0);
    k_gemm8<128><<<dim3(GEMM_MB, 4), 128, 0, s1>>>(x, W0, z, 256);

    // ---- s0: CSR build + norms + sim0 ----
    cudaMemsetAsync(cnt, 0, N_NODES * sizeof(int), 0);
    k_hist<<<400, 256>>>(row);
    k_scan_fast<<<1, 1024>>>();
    k_scatter<<<400, 256>>>(row, col);
    k_norms<128><<<NODE_WARP_BLOCKS, 256>>>(x);
    k_sim<128, 4><<<SIM4_BLOCKS, 256>>>(x);

    // ---- join gemm0, fused agg0 (rowsum+compact+gather) -> h1 ----
    cudaEventRecord(ev[1], s1);
    cudaStreamWaitEvent(0, ev[1], 0);
    k_aggf<true, true><<<NODE_WARP_BLOCKS, 256>>>(z, h1);

    // ---- layer 1: gemm1 on s1  ||  sim1+rowdeg1 (hidden) on s0 ----
    cudaEventRecord(ev[2], 0);
    cudaStreamWaitEvent(s1, ev[2], 0);
    k_gemm8<256><<<dim3(GEMM_MB, 4), 128, 0, s1>>>(h1, W1, z, 256);
    k_sim<256, 4><<<SIM4_BLOCKS, 256>>>(h1);
    k_rowdeg<<<NODE_WARP_BLOCKS, 256>>>();
    cudaEventRecord(ev[3], s1);
    cudaStreamWaitEvent(0, ev[3], 0);
    k_agg<true, true><<<NODE_WARP_BLOCKS, 256>>>(z, h2);

    // ---- layer 2: gemm16 on s1  ||  sim2 on s0; fused agg16 joins both ----
    cudaEventRecord(ev[4], 0);
    cudaStreamWaitEvent(s1, ev[4], 0);
    k_gemm16<<<(N_NODES + 63) / 64, 256, 0, s1>>>(h2, W2, z);
    cudaEventRecord(ev[5], s1);
    k_sim<256, 4><<<SIM4_BLOCKS, 256>>>(h2);
    cudaStreamWaitEvent(0, ev[5], 0);
    k_agg16f<<<NODE_WARP_BLOCKS, 256>>>(z, out);
}